// round 2
// baseline (speedup 1.0000x reference)
#include <cuda_runtime.h>

// GraphNorm: x (131072, 256) fp32, 64 graphs x 2048 rows x 256 units.
// Per (graph, unit): mean & population std over 2048 rows, then
// out = gamma * (x - mean)/(std + 1e-5) + beta.
//
// Block = (graph, 32-unit chunk), grid (8, 64), 1024 threads.
// 256-bit vector accesses throughout (sm_103 requires .v8.b32 for L2 evict
// hints anyway). Pass1 reads x with evict_last (slice stays in L2, 256KB/block,
// <=75MB concurrent), pass2 re-reads x + streams gamma/beta with evict_first
// and stores with st.cs so streaming operands don't thrash the resident x.

#define UNITS   256
#define BATCH   64
#define NPG     2048
#define UB      32              // units per block
#define NWARPS  32
#define THREADS 1024
#define VEC     8
#define ITERS   8               // 2048 rows / (32 warps * 8 row-subgroups)
#define EPS     1e-5f

__device__ __forceinline__ void ld_v8_evict_last(const float* p, float* r) {
    asm volatile("ld.global.L2::evict_last.v8.b32 {%0,%1,%2,%3,%4,%5,%6,%7}, [%8];"
                 : "=f"(r[0]), "=f"(r[1]), "=f"(r[2]), "=f"(r[3]),
                   "=f"(r[4]), "=f"(r[5]), "=f"(r[6]), "=f"(r[7])
                 : "l"(p));
}
__device__ __forceinline__ void ld_v8_evict_first(const float* p, float* r) {
    asm volatile("ld.global.L2::evict_first.v8.b32 {%0,%1,%2,%3,%4,%5,%6,%7}, [%8];"
                 : "=f"(r[0]), "=f"(r[1]), "=f"(r[2]), "=f"(r[3]),
                   "=f"(r[4]), "=f"(r[5]), "=f"(r[6]), "=f"(r[7])
                 : "l"(p));
}
__device__ __forceinline__ void st_v4_cs(float* p, float a, float b, float c, float d) {
    asm volatile("st.global.cs.v4.f32 [%0], {%1,%2,%3,%4};"
                 :: "l"(p), "f"(a), "f"(b), "f"(c), "f"(d));
}

__global__ void __launch_bounds__(THREADS)
graphnorm_kernel(const float* __restrict__ x,
                 const float* __restrict__ gamma,
                 const float* __restrict__ beta,
                 float* __restrict__ out)
{
    const int uc     = blockIdx.x;          // unit chunk 0..7
    const int g      = blockIdx.y;          // graph 0..63
    const int lane   = threadIdx.x & 31;
    const int w      = threadIdx.x >> 5;
    const int ug     = lane & 3;            // unit sub-group 0..3 (8 units each)
    const int rg     = lane >> 2;           // row sub-group 0..7

    // this thread's 8 units: uc*32 + ug*8 + [0..8)
    const size_t ubase = (size_t)uc * UB + (size_t)ug * VEC;
    // rows: w*8 + rg + i*256,  i = 0..7
    const int row0 = w * 8 + rg;
    const size_t gbase = (size_t)g * NPG * UNITS;

    // ---------------- pass 1: sum / sumsq ----------------
    float sum[VEC], sq[VEC];
    #pragma unroll
    for (int j = 0; j < VEC; ++j) { sum[j] = 0.f; sq[j] = 0.f; }

    #pragma unroll
    for (int i = 0; i < ITERS; ++i) {
        const int row = row0 + i * 256;
        float v[VEC];
        ld_v8_evict_last(x + gbase + (size_t)row * UNITS + ubase, v);
        #pragma unroll
        for (int j = 0; j < VEC; ++j) {
            sum[j] += v[j];
            sq[j] = fmaf(v[j], v[j], sq[j]);
        }
    }

    // warp reduction over the 8 row-subgroups (lane bits 2..4)
    #pragma unroll
    for (int m = 4; m <= 16; m <<= 1) {
        #pragma unroll
        for (int j = 0; j < VEC; ++j) {
            sum[j] += __shfl_xor_sync(0xffffffffu, sum[j], m);
            sq[j]  += __shfl_xor_sync(0xffffffffu, sq[j],  m);
        }
    }

    __shared__ float s_sum[NWARPS][UB];
    __shared__ float s_sq [NWARPS][UB];
    if (lane < 4) {
        #pragma unroll
        for (int j = 0; j < VEC; ++j) {
            s_sum[w][lane * VEC + j] = sum[j];
            s_sq [w][lane * VEC + j] = sq[j];
        }
    }
    __syncthreads();

    // tree reduce across 32 warps
    #pragma unroll
    for (int stride = NWARPS / 2; stride > 0; stride >>= 1) {
        if (w < stride && lane < 4) {
            #pragma unroll
            for (int j = 0; j < VEC; ++j) {
                const int u = lane * VEC + j;
                s_sum[w][u] += s_sum[w + stride][u];
                s_sq [w][u] += s_sq [w + stride][u];
            }
        }
        __syncthreads();
    }

    __shared__ float s_mean[UB], s_inv[UB];
    if (w == 0 && lane < 4) {
        const float invn = 1.0f / (float)NPG;
        #pragma unroll
        for (int j = 0; j < VEC; ++j) {
            const int u = lane * VEC + j;
            const float mean = s_sum[0][u] * invn;
            float var = fmaf(-mean, mean, s_sq[0][u] * invn);
            var = fmaxf(var, 0.0f);
            s_mean[u] = mean;
            s_inv [u] = 1.0f / (sqrtf(var) + EPS);
        }
    }
    __syncthreads();

    float mean[VEC], inv[VEC];
    #pragma unroll
    for (int j = 0; j < VEC; ++j) {
        const int u = ug * VEC + j;
        mean[j] = s_mean[u];
        inv [j] = s_inv [u];
    }

    // ---------------- pass 2: normalize + affine ----------------
    #pragma unroll
    for (int i = 0; i < ITERS; ++i) {
        const int row = row0 + i * 256;
        const size_t idx = gbase + (size_t)row * UNITS + ubase;
        float v[VEC], ga[VEC], be[VEC];
        ld_v8_evict_first(x     + idx, v);   // 2nd read: L2 hit, then drop
        ld_v8_evict_first(gamma + idx, ga);  // streaming
        ld_v8_evict_first(beta  + idx, be);  // streaming
        float o[VEC];
        #pragma unroll
        for (int j = 0; j < VEC; ++j)
            o[j] = fmaf((v[j] - mean[j]) * inv[j], ga[j], be[j]);
        st_v4_cs(out + idx,     o[0], o[1], o[2], o[3]);
        st_v4_cs(out + idx + 4, o[4], o[5], o[6], o[7]);
    }
}

extern "C" void kernel_launch(void* const* d_in, const int* in_sizes, int n_in,
                              void* d_out, int out_size) {
    const float* x     = (const float*)d_in[0];
    const float* gamma = (const float*)d_in[1];
    const float* beta  = (const float*)d_in[2];
    float* out = (float*)d_out;

    dim3 grid(UNITS / UB, BATCH);   // (8, 64)
    graphnorm_kernel<<<grid, THREADS>>>(x, gamma, beta, out);
}